// round 1
// baseline (speedup 1.0000x reference)
#include <cuda_runtime.h>
#include <math.h>

#define T 8192
#define C 512
#define II 64
#define E 32
#define KFB (E/2)
#define FULLMASK 0xffffffffu
#define NEGC (-3.3895313892515355e+38f)

// ---------------- device scratch (static globals; no runtime alloc) ----------
__device__ float g_rw[T * E];          // routing weights
__device__ int   g_idx[E * T];         // per-expert compacted token lists
__device__ int   g_cnt[E];             // per-expert active counts
__device__ float g_colnorm[E];         // ||sim[:,e]||
__device__ float g_sig[E];             // sigmoid(gates)
__device__ float g_H[(size_t)E * T * II];  // gelu(x@W1) per active slot (64 MB)

// ---------------- kernel 0: prep (col norms, sigmoid, counter reset) ---------
__global__ void prep_kernel(const float* __restrict__ sim,
                            const float* __restrict__ gates) {
    int w = threadIdx.x >> 5;   // expert
    int lane = threadIdx.x & 31;
    float s = 0.f;
    for (int c = lane; c < C; c += 32) {
        float v = sim[c * E + w];
        s = fmaf(v, v, s);
    }
    #pragma unroll
    for (int o = 16; o; o >>= 1) s += __shfl_xor_sync(FULLMASK, s, o);
    if (lane == 0) {
        g_colnorm[w] = fmaxf(sqrtf(s), 1e-12f);
        g_sig[w]     = 1.f / (1.f + expf(-gates[w]));
        g_cnt[w]     = 0;
    }
}

// ---------------- kernel 1: gating (1 warp per token; lane == expert) --------
__global__ __launch_bounds__(256) void gating_kernel(
    const float* __restrict__ x, const float* __restrict__ sim,
    float* __restrict__ pre_out, float* __restrict__ mask_out) {
    __shared__ float s_x[8 * C];
    __shared__ unsigned char s_act[8][E];

    int tid = threadIdx.x;
    int w = tid >> 5;         // token slot within block (0..7)
    int lane = tid & 31;      // expert id
    int t0 = blockIdx.x * 8;
    int t = t0 + w;

    // cooperative load of 8 contiguous token rows (4096 floats, coalesced)
    const float* xbase = x + (size_t)t0 * C;
    #pragma unroll
    for (int p = 0; p < 16; p++) s_x[tid + p * 256] = xbase[tid + p * 256];
    __syncthreads();

    const float* xw = s_x + w * C;
    float acc = 0.f, nsq = 0.f;
    #pragma unroll 8
    for (int c = 0; c < C; c++) {
        float xc = xw[c];                       // broadcast LDS
        acc = fmaf(xc, __ldg(&sim[c * E + lane]), acc);
        nsq = fmaf(xc, xc, nsq);                // redundant per lane, cheap
    }

    float xnorm = fmaxf(sqrtf(nsq), 1e-12f);
    float logit = acc / (xnorm * g_colnorm[lane]);
    float pre   = logit - g_sig[lane];
    float gated = fmaxf(pre, 0.f);

    unsigned act = __ballot_sync(FULLMASK, gated > 0.f);
    float maskv;
    if (act == 0u) {  // token inactive -> top-16 fallback on logits
        int rank = 0;
        #pragma unroll
        for (int j = 0; j < 32; j++) {
            float lj = __shfl_sync(FULLMASK, logit, j);
            rank += (lj > logit) || (lj == logit && j < lane);
        }
        maskv = (rank < KFB) ? 1.f : 0.f;
    } else {
        maskv = (gated > 0.f) ? 1.f : 0.f;   // STE forward (exactly 0/1)
    }

    float maskedv = (maskv > 0.f) ? gated : NEGC;
    float m = maskedv;
    #pragma unroll
    for (int o = 16; o; o >>= 1) m = fmaxf(m, __shfl_xor_sync(FULLMASK, m, o));
    float p = expf(maskedv - m);   // exp(NEG - m) underflows to exactly 0
    float ssum = p;
    #pragma unroll
    for (int o = 16; o; o >>= 1) ssum += __shfl_xor_sync(FULLMASK, ssum, o);
    float rw = p / ssum;

    pre_out[t * E + lane]  = pre;
    mask_out[t * E + lane] = maskv;
    g_rw[t * E + lane]     = rw;
    s_act[w][lane] = (maskv > 0.f) ? 1 : 0;
    __syncthreads();

    // block-aggregated compaction: one atomic per (block, expert)
    if (tid < E) {
        int e = tid;
        int cntl = 0;
        #pragma unroll
        for (int s2 = 0; s2 < 8; s2++) cntl += s_act[s2][e];
        if (cntl > 0) {
            int base = atomicAdd(&g_cnt[e], cntl);
            for (int s2 = 0; s2 < 8; s2++)
                if (s_act[s2][e]) g_idx[e * T + base++] = t0 + s2;
        }
    }
}

// ---------------- gelu (exact, matches approximate=False) --------------------
__device__ __forceinline__ float gelu_exact(float v) {
    return 0.5f * v * (1.0f + erff(v * 0.70710678118654752f));
}

// ---------------- kernel 2: GEMM1  H = gelu(Xg @ W1[e]) over active slots ----
// tile: M=128 slots, N=64 (=I), K=512 in chunks of 32. 256 threads, 8x4 micro.
__global__ __launch_bounds__(256) void gemm1_kernel(
    const float* __restrict__ x, const float* __restrict__ W1) {
    int e = blockIdx.y;
    int cnt = g_cnt[e];
    int m0 = blockIdx.x * 128;
    if (m0 >= cnt) return;

    __shared__ float Xs[32][129];   // [k][m], padded
    __shared__ float W1s[32 * 64];  // [k][i]
    __shared__ int toks[128];

    int tid = threadIdx.x;
    if (tid < 128) toks[tid] = (m0 + tid < cnt) ? g_idx[e * T + m0 + tid] : -1;
    __syncthreads();

    float accr[8][4];
    #pragma unroll
    for (int r = 0; r < 8; r++)
        #pragma unroll
        for (int c = 0; c < 4; c++) accr[r][c] = 0.f;

    int ty = tid >> 4, tx = tid & 15;
    int cc = tid & 31, mb = tid >> 5;

    for (int c0 = 0; c0 < C; c0 += 32) {
        #pragma unroll
        for (int p = 0; p < 16; p++) {
            int m = mb + p * 8;
            int tok = toks[m];
            Xs[cc][m] = (tok >= 0) ? __ldg(&x[(size_t)tok * C + c0 + cc]) : 0.f;
        }
        const float* w1p = W1 + ((size_t)e * C + c0) * II;
        #pragma unroll
        for (int p = 0; p < 8; p++) W1s[tid + p * 256] = w1p[tid + p * 256];
        __syncthreads();

        #pragma unroll
        for (int kk = 0; kk < 32; kk++) {
            float a[8], b[4];
            #pragma unroll
            for (int r = 0; r < 8; r++) a[r] = Xs[kk][ty * 8 + r];
            #pragma unroll
            for (int c = 0; c < 4; c++) b[c] = W1s[kk * 64 + tx * 4 + c];
            #pragma unroll
            for (int r = 0; r < 8; r++)
                #pragma unroll
                for (int c = 0; c < 4; c++) accr[r][c] = fmaf(a[r], b[c], accr[r][c]);
        }
        __syncthreads();
    }

    #pragma unroll
    for (int r = 0; r < 8; r++) {
        int slot = m0 + ty * 8 + r;
        if (slot < cnt) {
            float4 hv;
            hv.x = gelu_exact(accr[r][0]);
            hv.y = gelu_exact(accr[r][1]);
            hv.z = gelu_exact(accr[r][2]);
            hv.w = gelu_exact(accr[r][3]);
            *(float4*)&g_H[((size_t)e * T + slot) * II + tx * 4] = hv;
        }
    }
}

// ---------------- kernel 3: GEMM2  Y = H @ W2[e]; scatter to feo -------------
// tile: M=64 slots, N=128 (4 n-tiles over C=512), K=64 in 2 chunks of 32.
__global__ __launch_bounds__(256) void gemm2_kernel(
    const float* __restrict__ W2, float* __restrict__ feo) {
    int e = blockIdx.y;
    int cnt = g_cnt[e];
    int m0 = blockIdx.x * 64;
    if (m0 >= cnt) return;

    __shared__ float Hs[64][65];     // [i][m], padded
    __shared__ float W2s[32 * 128];  // [k][n]
    __shared__ int toks[64];

    int tid = threadIdx.x;
    if (tid < 64) toks[tid] = (m0 + tid < cnt) ? g_idx[e * T + m0 + tid] : -1;
    #pragma unroll
    for (int p = 0; p < 16; p++) {
        int idx = tid + p * 256;
        int m = idx >> 6, i = idx & 63;
        Hs[i][m] = (m0 + m < cnt) ? g_H[((size_t)e * T + m0 + m) * II + i] : 0.f;
    }
    __syncthreads();

    int ty = tid >> 4, tx = tid & 15;

    for (int n0 = 0; n0 < C; n0 += 128) {
        float accr[4][8];
        #pragma unroll
        for (int r = 0; r < 4; r++)
            #pragma unroll
            for (int c = 0; c < 8; c++) accr[r][c] = 0.f;

        for (int k0 = 0; k0 < II; k0 += 32) {
            #pragma unroll
            for (int p = 0; p < 16; p++) {
                int idx = tid + p * 256;
                W2s[idx] = W2[((size_t)e * II + k0 + (idx >> 7)) * C + n0 + (idx & 127)];
            }
            __syncthreads();

            #pragma unroll
            for (int kk = 0; kk < 32; kk++) {
                float a[4];
                #pragma unroll
                for (int r = 0; r < 4; r++) a[r] = Hs[k0 + kk][ty * 4 + r];
                float4 b0 = *(const float4*)&W2s[kk * 128 + tx * 8];
                float4 b1 = *(const float4*)&W2s[kk * 128 + tx * 8 + 4];
                #pragma unroll
                for (int r = 0; r < 4; r++) {
                    accr[r][0] = fmaf(a[r], b0.x, accr[r][0]);
                    accr[r][1] = fmaf(a[r], b0.y, accr[r][1]);
                    accr[r][2] = fmaf(a[r], b0.z, accr[r][2]);
                    accr[r][3] = fmaf(a[r], b0.w, accr[r][3]);
                    accr[r][4] = fmaf(a[r], b1.x, accr[r][4]);
                    accr[r][5] = fmaf(a[r], b1.y, accr[r][5]);
                    accr[r][6] = fmaf(a[r], b1.z, accr[r][6]);
                    accr[r][7] = fmaf(a[r], b1.w, accr[r][7]);
                }
            }
            __syncthreads();
        }

        #pragma unroll
        for (int r = 0; r < 4; r++) {
            int tok = toks[ty * 4 + r];
            if (tok >= 0) {
                float4* dst = (float4*)&feo[((size_t)tok * E + e) * C + n0 + tx * 8];
                dst[0] = make_float4(accr[r][0], accr[r][1], accr[r][2], accr[r][3]);
                dst[1] = make_float4(accr[r][4], accr[r][5], accr[r][6], accr[r][7]);
            }
        }
    }
}

// ---------------- kernel 4: finalize ------------------------------------------
// per token: zero inactive feo rows, accumulate final = sum_e rw*feo (fixed order
// over e -> deterministic, no atomics).
__global__ __launch_bounds__(128) void finalize_kernel(
    const float* __restrict__ maskp, float* __restrict__ feo,
    float* __restrict__ final_out) {
    int t = blockIdx.x;
    int tid = threadIdx.x;  // 128 threads * float4 = 512 cols
    float4 acc = make_float4(0.f, 0.f, 0.f, 0.f);
    #pragma unroll 1
    for (int e = 0; e < E; e++) {
        float mv = maskp[t * E + e];
        float4* row = (float4*)&feo[((size_t)t * E + e) * C];
        if (mv > 0.f) {
            float wv = g_rw[t * E + e];
            float4 v = row[tid];
            acc.x = fmaf(wv, v.x, acc.x);
            acc.y = fmaf(wv, v.y, acc.y);
            acc.z = fmaf(wv, v.z, acc.z);
            acc.w = fmaf(wv, v.w, acc.w);
        } else {
            row[tid] = make_float4(0.f, 0.f, 0.f, 0.f);
        }
    }
    ((float4*)&final_out[(size_t)t * C])[tid] = acc;
}

// ---------------- launch ------------------------------------------------------
extern "C" void kernel_launch(void* const* d_in, const int* in_sizes, int n_in,
                              void* d_out, int out_size) {
    const float* x     = (const float*)d_in[0];  // (T, C)
    const float* sim   = (const float*)d_in[1];  // (C, E)
    const float* gates = (const float*)d_in[2];  // (E,)
    const float* W1    = (const float*)d_in[3];  // (E, C, I)
    const float* W2    = (const float*)d_in[4];  // (E, I, C)

    float* out       = (float*)d_out;
    float* final_out = out;                              // T*C
    float* feo       = out + (size_t)T * C;              // T*E*C
    float* pre       = feo + (size_t)T * E * C;          // T*E
    float* maskp     = pre + (size_t)T * E;              // T*E

    prep_kernel<<<1, 1024>>>(sim, gates);
    gating_kernel<<<T / 8, 256>>>(x, sim, pre, maskp);
    dim3 g1(T / 128, E);
    gemm1_kernel<<<g1, 256>>>(x, W1);
    dim3 g2(T / 64, E);
    gemm2_kernel<<<g2, 256>>>(W2, feo);
    finalize_kernel<<<T, 128>>>(maskp, feo, final_out);
}

// round 3
// speedup vs baseline: 2.1984x; 2.1984x over previous
#include <cuda_runtime.h>
#include <cstdint>
#include <math.h>

#define T 8192
#define C 512
#define II 64
#define E 32
#define KFB (E/2)
#define FULLMASK 0xffffffffu
#define NEGC (-3.3895313892515355e+38f)

// ---------------- device scratch ----------------
__device__ float g_rw[T * E];
__device__ int   g_idx[E * T];
__device__ int   g_cnt[E];
__device__ float g_colnorm[E];
__device__ float g_sig[E];
__device__ float g_H[(size_t)E * T * II];     // gelu(x@W1), tf32-rounded values
__device__ float g_W1t[(size_t)E * II * C];   // [e][i][c]  K-major, tf32-rounded
__device__ float g_W2t[(size_t)E * C * II];   // [e][c][i]  K-major, tf32-rounded

// ---------------- helpers ----------------
__device__ __forceinline__ float to_tf32(float f) {
    uint32_t u;
    asm("cvt.rna.tf32.f32 %0, %1;" : "=r"(u) : "f"(f));
    return __uint_as_float(u);
}

// D += A(16x8, row) * B(8x8, col)  tf32 inputs, f32 accum
__device__ __forceinline__ void mma16n8k8(float* d, const uint32_t* a, const uint32_t* b) {
    asm volatile(
        "mma.sync.aligned.m16n8k8.row.col.f32.tf32.tf32.f32 "
        "{%0,%1,%2,%3}, {%4,%5,%6,%7}, {%8,%9}, {%0,%1,%2,%3};"
        : "+f"(d[0]), "+f"(d[1]), "+f"(d[2]), "+f"(d[3])
        : "r"(a[0]), "r"(a[1]), "r"(a[2]), "r"(a[3]), "r"(b[0]), "r"(b[1]));
}

__device__ __forceinline__ float gelu_exact(float v) {
    return 0.5f * v * (1.0f + erff(v * 0.70710678118654752f));
}

// ---------------- kernel 0: prep ----------------
__global__ void prep_kernel(const float* __restrict__ sim, const float* __restrict__ gates) {
    int w = threadIdx.x >> 5;
    int lane = threadIdx.x & 31;
    float s = 0.f;
    for (int c = lane; c < C; c += 32) {
        float v = sim[c * E + w];
        s = fmaf(v, v, s);
    }
    #pragma unroll
    for (int o = 16; o; o >>= 1) s += __shfl_xor_sync(FULLMASK, s, o);
    if (lane == 0) {
        g_colnorm[w] = fmaxf(sqrtf(s), 1e-12f);
        g_sig[w]     = 1.f / (1.f + expf(-gates[w]));
        g_cnt[w]     = 0;
    }
}

// ---------------- weight transposes (K-major + tf32 rounding) ----------------
__global__ __launch_bounds__(256) void transpose_w1(const float* __restrict__ W1) {
    __shared__ float t[32][33];
    int e = blockIdx.z, c0 = blockIdx.x * 32, i0 = blockIdx.y * 32;
    int tx = threadIdx.x & 31, ty = threadIdx.x >> 5;
    #pragma unroll
    for (int j = 0; j < 32; j += 8)
        t[ty + j][tx] = W1[((size_t)e * C + c0 + ty + j) * II + i0 + tx];
    __syncthreads();
    #pragma unroll
    for (int j = 0; j < 32; j += 8)
        g_W1t[((size_t)e * II + i0 + ty + j) * C + c0 + tx] = to_tf32(t[tx][ty + j]);
}
__global__ __launch_bounds__(256) void transpose_w2(const float* __restrict__ W2) {
    __shared__ float t[32][33];
    int e = blockIdx.z, i0 = blockIdx.x * 32, c0 = blockIdx.y * 32;
    int tx = threadIdx.x & 31, ty = threadIdx.x >> 5;
    #pragma unroll
    for (int j = 0; j < 32; j += 8)
        t[ty + j][tx] = W2[((size_t)e * II + i0 + ty + j) * C + c0 + tx];
    __syncthreads();
    #pragma unroll
    for (int j = 0; j < 32; j += 8)
        g_W2t[((size_t)e * C + c0 + ty + j) * II + i0 + tx] = to_tf32(t[tx][ty + j]);
}

// ---------------- kernel 1: gating ----------------
__global__ __launch_bounds__(256) void gating_kernel(
    const float* __restrict__ x, const float* __restrict__ sim,
    float* __restrict__ pre_out, float* __restrict__ mask_out) {
    __shared__ float s_x[8 * C];
    __shared__ unsigned char s_act[8][E];

    int tid = threadIdx.x;
    int w = tid >> 5;
    int lane = tid & 31;
    int t0 = blockIdx.x * 8;
    int t = t0 + w;

    const float* xbase = x + (size_t)t0 * C;
    #pragma unroll
    for (int p = 0; p < 16; p++) s_x[tid + p * 256] = xbase[tid + p * 256];
    __syncthreads();

    const float* xw = s_x + w * C;
    float acc = 0.f, nsq = 0.f;
    #pragma unroll 8
    for (int c = 0; c < C; c++) {
        float xc = xw[c];
        acc = fmaf(xc, __ldg(&sim[c * E + lane]), acc);
        nsq = fmaf(xc, xc, nsq);
    }

    float xnorm = fmaxf(sqrtf(nsq), 1e-12f);
    float logit = acc / (xnorm * g_colnorm[lane]);
    float pre   = logit - g_sig[lane];
    float gated = fmaxf(pre, 0.f);

    unsigned act = __ballot_sync(FULLMASK, gated > 0.f);
    float maskv;
    if (act == 0u) {
        int rank = 0;
        #pragma unroll
        for (int j = 0; j < 32; j++) {
            float lj = __shfl_sync(FULLMASK, logit, j);
            rank += (lj > logit) || (lj == logit && j < lane);
        }
        maskv = (rank < KFB) ? 1.f : 0.f;
    } else {
        maskv = (gated > 0.f) ? 1.f : 0.f;
    }

    float maskedv = (maskv > 0.f) ? gated : NEGC;
    float m = maskedv;
    #pragma unroll
    for (int o = 16; o; o >>= 1) m = fmaxf(m, __shfl_xor_sync(FULLMASK, m, o));
    float p = expf(maskedv - m);
    float ssum = p;
    #pragma unroll
    for (int o = 16; o; o >>= 1) ssum += __shfl_xor_sync(FULLMASK, ssum, o);
    float rw = p / ssum;

    pre_out[t * E + lane]  = pre;
    mask_out[t * E + lane] = maskv;
    g_rw[t * E + lane]     = rw;
    s_act[w][lane] = (maskv > 0.f) ? 1 : 0;
    __syncthreads();

    if (tid < E) {
        int e = tid;
        int cntl = 0;
        #pragma unroll
        for (int s2 = 0; s2 < 8; s2++) cntl += s_act[s2][e];
        if (cntl > 0) {
            int base = atomicAdd(&g_cnt[e], cntl);
            for (int s2 = 0; s2 < 8; s2++)
                if (s_act[s2][e]) g_idx[e * T + base++] = t0 + s2;
        }
    }
}

// ---------------- GEMM1 (mma.sync tf32): H = gelu(Xg @ W1t^T) ----------------
// block: (128 tokens, expert). warps 4x2, warp tile 32x32. K=512 in 8 chunks of 64.
#define XS_STRIDE 68
#define G1_OFF_X  512
#define G1_OFF_W  (512 + 128 * XS_STRIDE * 4)
#define G1_SMEM   (G1_OFF_W + 64 * XS_STRIDE * 4)

__global__ __launch_bounds__(256) void gemm1_mma(const float* __restrict__ x) {
    int e = blockIdx.y;
    int cnt = g_cnt[e];
    int m0 = blockIdx.x * 128;
    if (m0 >= cnt) return;

    extern __shared__ char smem[];
    int* toks = (int*)smem;
    float* Xs = (float*)(smem + G1_OFF_X);
    float* Ws = (float*)(smem + G1_OFF_W);

    int tid = threadIdx.x;
    if (tid < 128) toks[tid] = (m0 + tid < cnt) ? g_idx[e * T + m0 + tid] : -1;
    __syncthreads();

    int wid = tid >> 5, lane = tid & 31;
    int warpM = wid >> 1, warpN = wid & 1;
    int rbase = warpM * 32, nbase = warpN * 32;
    int lr = lane >> 2, lc = lane & 3;

    float d[2][4][4];
    #pragma unroll
    for (int mt = 0; mt < 2; mt++)
        #pragma unroll
        for (int nt = 0; nt < 4; nt++)
            #pragma unroll
            for (int i = 0; i < 4; i++) d[mt][nt][i] = 0.f;

    for (int kc = 0; kc < 8; kc++) {
        // stage X chunk (128 rows x 64 cols), tf32-rounded
        #pragma unroll
        for (int p = 0; p < 8; p++) {
            int fi = tid + (p << 8);
            int r = fi >> 4, q = fi & 15;
            int tok = toks[r];
            float4 v = make_float4(0.f, 0.f, 0.f, 0.f);
            if (tok >= 0) v = *(const float4*)(x + (size_t)tok * C + kc * 64 + q * 4);
            float4 u = make_float4(to_tf32(v.x), to_tf32(v.y), to_tf32(v.z), to_tf32(v.w));
            *(float4*)(Xs + r * XS_STRIDE + q * 4) = u;
        }
        // stage W chunk (64 rows x 64 cols), already tf32
        #pragma unroll
        for (int p = 0; p < 4; p++) {
            int fi = tid + (p << 8);
            int i = fi >> 4, q = fi & 15;
            float4 v = *(const float4*)(g_W1t + ((size_t)e * II + i) * C + kc * 64 + q * 4);
            *(float4*)(Ws + i * XS_STRIDE + q * 4) = v;
        }
        __syncthreads();

        #pragma unroll
        for (int ks = 0; ks < 8; ks++) {
            int k0 = ks * 8;
            uint32_t afr[2][4], bfr[4][2];
            #pragma unroll
            for (int mt = 0; mt < 2; mt++) {
                int row = rbase + mt * 16 + lr;
                afr[mt][0] = __float_as_uint(Xs[row * XS_STRIDE + k0 + lc]);
                afr[mt][1] = __float_as_uint(Xs[(row + 8) * XS_STRIDE + k0 + lc]);
                afr[mt][2] = __float_as_uint(Xs[row * XS_STRIDE + k0 + lc + 4]);
                afr[mt][3] = __float_as_uint(Xs[(row + 8) * XS_STRIDE + k0 + lc + 4]);
            }
            #pragma unroll
            for (int nt = 0; nt < 4; nt++) {
                int col = nbase + nt * 8 + lr;
                bfr[nt][0] = __float_as_uint(Ws[col * XS_STRIDE + k0 + lc]);
                bfr[nt][1] = __float_as_uint(Ws[col * XS_STRIDE + k0 + lc + 4]);
            }
            #pragma unroll
            for (int mt = 0; mt < 2; mt++)
                #pragma unroll
                for (int nt = 0; nt < 4; nt++)
                    mma16n8k8(d[mt][nt], afr[mt], bfr[nt]);
        }
        __syncthreads();
    }

    // epilogue: gelu + tf32 round, store valid rows to g_H
    #pragma unroll
    for (int mt = 0; mt < 2; mt++) {
        int slot0 = m0 + rbase + mt * 16 + lr;
        int slot1 = slot0 + 8;
        #pragma unroll
        for (int nt = 0; nt < 4; nt++) {
            int col = nbase + nt * 8 + lc * 2;
            if (slot0 < cnt) {
                float2 v = make_float2(to_tf32(gelu_exact(d[mt][nt][0])),
                                       to_tf32(gelu_exact(d[mt][nt][1])));
                *(float2*)&g_H[((size_t)e * T + slot0) * II + col] = v;
            }
            if (slot1 < cnt) {
                float2 v = make_float2(to_tf32(gelu_exact(d[mt][nt][2])),
                                       to_tf32(gelu_exact(d[mt][nt][3])));
                *(float2*)&g_H[((size_t)e * T + slot1) * II + col] = v;
            }
        }
    }
}

// ---------------- GEMM2 (mma.sync tf32): Y = H @ W2t^T -> scatter feo ----------------
// block: (128 tokens, expert, 128-col chunk). warps 4x2, warp tile 32x64. K=64.
#define G2_OFF_H  512
#define G2_OFF_W  (512 + 128 * XS_STRIDE * 4)
#define G2_SMEM   (G2_OFF_W + 128 * XS_STRIDE * 4)

__global__ __launch_bounds__(256) void gemm2_mma(float* __restrict__ feo) {
    int e = blockIdx.y;
    int cnt = g_cnt[e];
    int m0 = blockIdx.x * 128;
    if (m0 >= cnt) return;
    int n0 = blockIdx.z * 128;

    extern __shared__ char smem[];
    int* toks = (int*)smem;
    float* Hs = (float*)(smem + G2_OFF_H);
    float* Ws = (float*)(smem + G2_OFF_W);

    int tid = threadIdx.x;
    if (tid < 128) toks[tid] = (m0 + tid < cnt) ? g_idx[e * T + m0 + tid] : -1;

    // stage H (128 rows x 64), already tf32-rounded values
    #pragma unroll
    for (int p = 0; p < 8; p++) {
        int fi = tid + (p << 8);
        int r = fi >> 4, q = fi & 15;
        float4 v = make_float4(0.f, 0.f, 0.f, 0.f);
        if (m0 + r < cnt) v = *(const float4*)&g_H[((size_t)e * T + m0 + r) * II + q * 4];
        *(float4*)(Hs + r * XS_STRIDE + q * 4) = v;
    }
    // stage W2t chunk (128 n rows x 64 k), already tf32
    #pragma unroll
    for (int p = 0; p < 8; p++) {
        int fi = tid + (p << 8);
        int n = fi >> 4, q = fi & 15;
        float4 v = *(const float4*)(g_W2t + ((size_t)e * C + n0 + n) * II + q * 4);
        *(float4*)(Ws + n * XS_STRIDE + q * 4) = v;
    }
    __syncthreads();

    int wid = tid >> 5, lane = tid & 31;
    int warpM = wid >> 1, warpN = wid & 1;
    int rbase = warpM * 32, nbase = warpN * 64;
    int lr = lane >> 2, lc = lane & 3;

    float d[2][8][4];
    #pragma unroll
    for (int mt = 0; mt < 2; mt++)
        #pragma unroll
        for (int nt = 0; nt < 8; nt++)
            #pragma unroll
            for (int i = 0; i < 4; i++) d[mt][nt][i] = 0.f;

    #pragma unroll
    for (int ks = 0; ks < 8; ks++) {
        int k0 = ks * 8;
        uint32_t afr[2][4], bfr[8][2];
        #pragma unroll
        for (int mt = 0; mt < 2; mt++) {
            int row = rbase + mt * 16 + lr;
            afr[mt][0] = __float_as_uint(Hs[row * XS_STRIDE + k0 + lc]);
            afr[mt][1] = __float_as_uint(Hs[(row + 8) * XS_STRIDE + k0 + lc]);
            afr[mt][2] = __float_as_uint(Hs[row * XS_STRIDE + k0 + lc + 4]);
            afr[mt][3] = __float_as_uint(Hs[(row + 8) * XS_STRIDE + k0 + lc + 4]);
        }
        #pragma unroll
        for (int nt = 0; nt < 8; nt++) {
            int col = nbase + nt * 8 + lr;
            bfr[nt][0] = __float_as_uint(Ws[col * XS_STRIDE + k0 + lc]);
            bfr[nt][1] = __float_as_uint(Ws[col * XS_STRIDE + k0 + lc + 4]);
        }
        #pragma unroll
        for (int mt = 0; mt < 2; mt++)
            #pragma unroll
            for (int nt = 0; nt < 8; nt++)
                mma16n8k8(d[mt][nt], afr[mt], bfr[nt]);
    }

    // epilogue: scatter valid rows to feo
    #pragma unroll
    for (int mt = 0; mt < 2; mt++) {
        int slot0 = rbase + mt * 16 + lr;
        int slot1 = slot0 + 8;
        int tok0 = toks[slot0];
        int tok1 = toks[slot1];
        #pragma unroll
        for (int nt = 0; nt < 8; nt++) {
            int col = n0 + nbase + nt * 8 + lc * 2;
            if (tok0 >= 0)
                *(float2*)&feo[((size_t)tok0 * E + e) * C + col] =
                    make_float2(d[mt][nt][0], d[mt][nt][1]);
            if (tok1 >= 0)
                *(float2*)&feo[((size_t)tok1 * E + e) * C + col] =
                    make_float2(d[mt][nt][2], d[mt][nt][3]);
        }
    }
}

// ---------------- finalize ----------------
__global__ __launch_bounds__(128) void finalize_kernel(
    const float* __restrict__ maskp, float* __restrict__ feo,
    float* __restrict__ final_out) {
    int t = blockIdx.x;
    int tid = threadIdx.x;
    float4 acc = make_float4(0.f, 0.f, 0.f, 0.f);
    #pragma unroll 1
    for (int e = 0; e < E; e++) {
        float mv = maskp[t * E + e];
        float4* row = (float4*)&feo[((size_t)t * E + e) * C];
        if (mv > 0.f) {
            float wv = g_rw[t * E + e];
            float4 v = row[tid];
            acc.x = fmaf(wv, v.x, acc.x);
            acc.y = fmaf(wv, v.y, acc.y);
            acc.z = fmaf(wv, v.z, acc.z);
            acc.w = fmaf(wv, v.w, acc.w);
        } else {
            row[tid] = make_float4(0.f, 0.f, 0.f, 0.f);
        }
    }
    ((float4*)&final_out[(size_t)t * C])[tid] = acc;
}

// ---------------- launch ----------------
extern "C" void kernel_launch(void* const* d_in, const int* in_sizes, int n_in,
                              void* d_out, int out_size) {
    const float* x     = (const float*)d_in[0];
    const float* sim   = (const float*)d_in[1];
    const float* gates = (const float*)d_in[2];
    const float* W1    = (const float*)d_in[3];
    const float* W2    = (const float*)d_in[4];

    float* out       = (float*)d_out;
    float* final_out = out;
    float* feo       = out + (size_t)T * C;
    float* pre       = feo + (size_t)T * E * C;
    float* maskp     = pre + (size_t)T * E;

    cudaFuncSetAttribute(gemm1_mma, cudaFuncAttributeMaxDynamicSharedMemorySize, G1_SMEM);
    cudaFuncSetAttribute(gemm2_mma, cudaFuncAttributeMaxDynamicSharedMemorySize, G2_SMEM);

    prep_kernel<<<1, 1024>>>(sim, gates);
    transpose_w1<<<dim3(C / 32, II / 32, E), 256>>>(W1);
    transpose_w2<<<dim3(II / 32, C / 32, E), 256>>>(W2);
    gating_kernel<<<T / 8, 256>>>(x, sim, pre, maskp);
    gemm1_mma<<<dim3(T / 128, E), 256, G1_SMEM>>>(x);
    gemm2_mma<<<dim3(T / 128, E, C / 128), 256, G2_SMEM>>>(feo);
    finalize_kernel<<<T, 128>>>(maskp, feo, final_out);
}